// round 7
// baseline (speedup 1.0000x reference)
#include <cuda_runtime.h>
#include <cuda_bf16.h>
#include <math.h>

// Problem constants
#define BB 64
#define TT 1000
#define NN 512
#define G3 1536
#define GRID_SCAN 128
#define SCAN_THREADS 512

// ---------------------------------------------------------------------------
// f32x2 packed-FMA helpers (PTX-only; ptxas never auto-fuses)
// ---------------------------------------------------------------------------
__device__ __forceinline__ unsigned long long dup2(float x) {
    unsigned long long r;
    asm("mov.b64 %0, {%1, %1};" : "=l"(r) : "f"(x));
    return r;
}
__device__ __forceinline__ void fma2(unsigned long long& d,
                                     unsigned long long a,
                                     unsigned long long b) {
    asm("fma.rn.f32x2 %0, %1, %2, %0;" : "+l"(d) : "l"(a), "l"(b));
}
__device__ __forceinline__ void add2(unsigned long long& d, unsigned long long a) {
    asm("add.rn.f32x2 %0, %0, %1;" : "+l"(d) : "l"(a));
}
__device__ __forceinline__ float2 unpack2(unsigned long long v) {
    float2 f;
    asm("mov.b64 {%0, %1}, %2;" : "=f"(f.x), "=f"(f.y) : "l"(v));
    return f;
}

// ---------------------------------------------------------------------------
// Scratch. Barrier counter and generation flag on SEPARATE 128B L2 lines
// (same-line sharing caused ~18us/step LTS serialization in R4/R5).
// ---------------------------------------------------------------------------
struct __align__(128) Pad128 { unsigned v; unsigned pad[31]; };
__device__ Pad128   g_count;                        // arrivals (RMW line)
__device__ Pad128   g_gen;                          // generation (read-mostly line)
__device__ float    g_xproj[(size_t)BB * TT * G3];  // [B][T][3N]
__device__ float    g_ht[2][NN * BB];               // transposed hidden [k][b]

// ---------------------------------------------------------------------------
// Kernel 1: x_proj = h_enc @ W_ih^T + b_ih. 128x128x16 tiles, 8x8 microtile,
// f32x2-packed j. Block (0,0) also resets barrier + zeroes h0 (every replay).
// ---------------------------------------------------------------------------
__global__ void __launch_bounds__(256) xproj_kernel(
    const float* __restrict__ A,     // [64000][512]
    const float* __restrict__ Wih,   // [1536][512]
    const float* __restrict__ bih,   // [1536]
    float* __restrict__ C)           // [64000][1536]
{
    __shared__ float As[16][128];
    __shared__ float Bs[16][128];

    const int tid   = threadIdx.x;
    const int mBase = blockIdx.y * 128;
    const int nBase = blockIdx.x * 128;
    const int tx = tid & 15;
    const int ty = tid >> 4;

    if (blockIdx.x == 0 && blockIdx.y == 0) {
        if (tid == 0) { g_count.v = 0u; g_gen.v = 0u; }
        for (int j = tid; j < NN * BB; j += 256) g_ht[0][j] = 0.0f;
    }

    unsigned long long acc2[8][4];
#pragma unroll
    for (int i = 0; i < 8; i++)
#pragma unroll
        for (int j = 0; j < 4; j++) acc2[i][j] = 0ull;

    const int lr = tid >> 2;
    const int lk = (tid & 3) << 2;
    const float* Aptr = A   + (size_t)(mBase + lr) * NN + lk;
    const float* Bptr = Wih + (size_t)(nBase + lr) * NN + lk;

    for (int kt = 0; kt < NN; kt += 16) {
        const float4 a0 = *(const float4*)(Aptr + kt);
        const float4 a1 = *(const float4*)(Aptr + 64 * NN + kt);
        const float4 b0 = *(const float4*)(Bptr + kt);
        const float4 b1 = *(const float4*)(Bptr + 64 * NN + kt);
        __syncthreads();
        As[lk + 0][lr] = a0.x; As[lk + 1][lr] = a0.y; As[lk + 2][lr] = a0.z; As[lk + 3][lr] = a0.w;
        As[lk + 0][64 + lr] = a1.x; As[lk + 1][64 + lr] = a1.y; As[lk + 2][64 + lr] = a1.z; As[lk + 3][64 + lr] = a1.w;
        Bs[lk + 0][lr] = b0.x; Bs[lk + 1][lr] = b0.y; Bs[lk + 2][lr] = b0.z; Bs[lk + 3][lr] = b0.w;
        Bs[lk + 0][64 + lr] = b1.x; Bs[lk + 1][64 + lr] = b1.y; Bs[lk + 2][64 + lr] = b1.z; Bs[lk + 3][64 + lr] = b1.w;
        __syncthreads();
#pragma unroll
        for (int k = 0; k < 16; k++) {
            float af[8];
            *(float4*)&af[0] = *(const float4*)&As[k][ty * 4];
            *(float4*)&af[4] = *(const float4*)&As[k][64 + ty * 4];
            unsigned long long b2[4];
            *(uint4*)&b2[0] = *(const uint4*)&Bs[k][tx * 4];
            *(uint4*)&b2[2] = *(const uint4*)&Bs[k][64 + tx * 4];
#pragma unroll
            for (int i = 0; i < 8; i++) {
                const unsigned long long ad = dup2(af[i]);
#pragma unroll
                for (int j = 0; j < 4; j++) fma2(acc2[i][j], ad, b2[j]);
            }
        }
    }

    float bias[8];
#pragma unroll
    for (int j = 0; j < 8; j++) {
        int col = nBase + ((j < 4) ? (tx * 4 + j) : (64 + tx * 4 + (j - 4)));
        bias[j] = __ldg(&bih[col]);
    }
#pragma unroll
    for (int i = 0; i < 8; i++) {
        float a[8];
#pragma unroll
        for (int j = 0; j < 4; j++) {
            const float2 v = unpack2(acc2[i][j]);
            a[2 * j] = v.x; a[2 * j + 1] = v.y;
        }
        int row = mBase + ((i < 4) ? (ty * 4 + i) : (64 + ty * 4 + (i - 4)));
        float* cp = C + (size_t)row * G3 + nBase;
        *(float4*)(cp + tx * 4) =
            make_float4(a[0] + bias[0], a[1] + bias[1], a[2] + bias[2], a[3] + bias[3]);
        *(float4*)(cp + 64 + tx * 4) =
            make_float4(a[4] + bias[4], a[5] + bias[5], a[6] + bias[6], a[7] + bias[7]);
    }
}

// ---------------------------------------------------------------------------
// Kernel 2: persistent cooperative GRU scan.
//   128 CTAs x 512 threads (16 warps/SM). thread=(kq,nn,b2): k-chunk kq*128,
//   n-col n0+nn, batch pair 2*b2. Hidden state goes through L2 ONLY
//   (__ldcg/__stcg) -> no L1 staleness, no CCTL.IVALL fences; ordering via
//   scoped acquire/release atomics in the grid barrier.
// ---------------------------------------------------------------------------
__global__ void __launch_bounds__(SCAN_THREADS) gru_scan_kernel(
    const float* __restrict__ Whh,   // [1536][512]
    const float* __restrict__ bhh,   // [1536]
    float* __restrict__ out)         // [B][T][N]
{
    __shared__ unsigned long long wsd[12][514];        // dup'd W: [gate*4+jn][k]
    __shared__ float xs[3][4][64];                     // x_t: [gate][nn][b]
    __shared__ unsigned long long red[4][3][4][32];    // [kq][gate][nn][b2]
    __shared__ float hs[4][64];                        // h_new: [nn][b]

    const int tid = threadIdx.x;
    const int n0  = blockIdx.x * 4;
    const int kq  = tid >> 7;          // 0..3
    const int nn  = (tid >> 5) & 3;    // 0..3
    const int b2  = tid & 31;          // batch pair

    // Load + duplicate W_hh slice once (coalesced scalar loads along k)
    for (int i = tid; i < 12 * 512; i += SCAN_THREADS) {
        const int row = i >> 9;          // gate*4 + jn
        const int k   = i & 511;
        const int gate = row >> 2;
        const int jn   = row & 3;
        wsd[row][k] = dup2(__ldg(&Whh[(size_t)(gate * NN + n0 + jn) * NN + k]));
    }

    // Epilogue biases: tid<128 threads, en = tid>>5
    float bhr = 0.f, bhz = 0.f, bhn = 0.f;
    if (tid < 128) {
        const int en = tid >> 5;
        bhr = __ldg(&bhh[n0 + en]);
        bhz = __ldg(&bhh[NN + n0 + en]);
        bhn = __ldg(&bhh[2 * NN + n0 + en]);
    }

    const unsigned long long* wr = &wsd[nn][kq * 128];
    const unsigned long long* wz = &wsd[4 + nn][kq * 128];
    const unsigned long long* wn = &wsd[8 + nn][kq * 128];
    __syncthreads();

    for (int t = 0; t < TT; t++) {
        const float* hcur = g_ht[t & 1];
        float*       hnxt = g_ht[(t & 1) ^ 1];

        // Stage x_proj[:, t, slice] into SMEM (immutable data; L1 ok)
        if (tid < 192) {
            const int grp = tid >> 6;
            const int bb  = tid & 63;
            const float4 xv = __ldg((const float4*)(
                g_xproj + (size_t)(bb * TT + t) * G3 + grp * NN + n0));
            xs[grp][0][bb] = xv.x; xs[grp][1][bb] = xv.y;
            xs[grp][2][bb] = xv.z; xs[grp][3][bb] = xv.w;
        }

        // Partial gates over this thread's 128-k chunk, 2 batches (f32x2)
        unsigned long long ar = 0ull, az = 0ull, aq = 0ull;
        const float* hk = hcur + kq * 128 * BB + b2 * 2;
#pragma unroll 4
        for (int k = 0; k < 128; k += 2) {
            const unsigned long long h0 =
                __ldcg((const unsigned long long*)(hk + (size_t)(k + 0) * BB));
            const unsigned long long h1 =
                __ldcg((const unsigned long long*)(hk + (size_t)(k + 1) * BB));
            const ulonglong2 w0 = *(const ulonglong2*)&wr[k];
            const ulonglong2 w1 = *(const ulonglong2*)&wz[k];
            const ulonglong2 w2 = *(const ulonglong2*)&wn[k];
            fma2(ar, h0, w0.x); fma2(ar, h1, w0.y);
            fma2(az, h0, w1.x); fma2(az, h1, w1.y);
            fma2(aq, h0, w2.x); fma2(aq, h1, w2.y);
        }
        red[kq][0][nn][b2] = ar;
        red[kq][1][nn][b2] = az;
        red[kq][2][nn][b2] = aq;
        __syncthreads();

        // Epilogue: 128 threads, each finishes 2 batches for one n-column
        if (tid < 128) {
            const int en = tid >> 5;
            const int eb = tid & 31;
            unsigned long long sr = red[0][0][en][eb];
            unsigned long long sz = red[0][1][en][eb];
            unsigned long long sq = red[0][2][en][eb];
#pragma unroll
            for (int q = 1; q < 4; q++) {
                add2(sr, red[q][0][en][eb]);
                add2(sz, red[q][1][en][eb]);
                add2(sq, red[q][2][en][eb]);
            }
            const float2 arf = unpack2(sr);
            const float2 azf = unpack2(sz);
            const float2 aqf = unpack2(sq);
            const float2 hp = *(const float2*)(hcur + (n0 + en) * BB + eb * 2);
            const float2 xr = *(const float2*)&xs[0][en][eb * 2];
            const float2 xz = *(const float2*)&xs[1][en][eb * 2];
            const float2 xn = *(const float2*)&xs[2][en][eb * 2];

            const float r0  = 1.0f / (1.0f + __expf(-(xr.x + arf.x + bhr)));
            const float z0  = 1.0f / (1.0f + __expf(-(xz.x + azf.x + bhz)));
            const float n0v = tanhf(xn.x + r0 * (aqf.x + bhn));
            hs[en][eb * 2 + 0] = (1.0f - z0) * n0v + z0 * hp.x;

            const float r1  = 1.0f / (1.0f + __expf(-(xr.y + arf.y + bhr)));
            const float z1  = 1.0f / (1.0f + __expf(-(xz.y + azf.y + bhz)));
            const float n1v = tanhf(xn.y + r1 * (aqf.y + bhn));
            hs[en][eb * 2 + 1] = (1.0f - z1) * n1v + z1 * hp.y;
        }
        __syncthreads();

        // Writeback: out (plain) + h state (L2-only via stcg)
        if (tid < 64) {
            const int b = tid;
            *(float4*)(out + (size_t)(b * TT + t) * NN + n0) =
                make_float4(hs[0][b], hs[1][b], hs[2][b], hs[3][b]);
        } else if (tid < 128) {
            const int rr  = (tid - 64) >> 4;
            const int seg = (tid - 64) & 15;
            __stcg((float4*)(hnxt + (n0 + rr) * BB + seg * 4),
                   *(const float4*)&hs[rr][seg * 4]);
        }
        __syncthreads();

        // Grid barrier: acq_rel arrival on g_count, release-publish g_gen,
        // acquire-poll. No CCTL.IVALL anywhere (state is L2-only).
        if (t < TT - 1) {
            if (tid == 0) {
                const unsigned target = (unsigned)(t + 1);
                unsigned arrived;
                asm volatile("atom.acq_rel.gpu.global.add.u32 %0, [%1], %2;"
                             : "=r"(arrived) : "l"(&g_count.v), "r"(1u) : "memory");
                if (arrived + 1u == target * (unsigned)GRID_SCAN) {
                    asm volatile("st.release.gpu.global.u32 [%0], %1;"
                                 :: "l"(&g_gen.v), "r"(target) : "memory");
                } else {
                    unsigned g;
                    while (true) {
                        asm volatile("ld.acquire.gpu.global.u32 %0, [%1];"
                                     : "=r"(g) : "l"(&g_gen.v) : "memory");
                        if (g >= target) break;
                        __nanosleep(64);
                    }
                }
            }
            __syncthreads();
        }
    }
}

// ---------------------------------------------------------------------------
// Launch
// ---------------------------------------------------------------------------
extern "C" void kernel_launch(void* const* d_in, const int* in_sizes, int n_in,
                              void* d_out, int out_size) {
    const float* h_enc = (const float*)d_in[0];
    const float* W_ih  = (const float*)d_in[1];
    const float* W_hh  = (const float*)d_in[2];
    const float* b_ih  = (const float*)d_in[3];
    const float* b_hh  = (const float*)d_in[4];
    float* out = (float*)d_out;

    float* xproj_ptr = nullptr;
    cudaGetSymbolAddress((void**)&xproj_ptr, g_xproj);

    dim3 grid(G3 / 128, (BB * TT) / 128);
    xproj_kernel<<<grid, 256>>>(h_enc, W_ih, b_ih, xproj_ptr);
    gru_scan_kernel<<<GRID_SCAN, SCAN_THREADS>>>(W_hh, b_hh, out);
}

// round 8
// speedup vs baseline: 1.2873x; 1.2873x over previous
#include <cuda_runtime.h>
#include <cuda_bf16.h>
#include <math.h>

// Problem constants
#define BB 64
#define TT 1000
#define NN 512
#define G3 1536
#define GRID_SCAN 128

// ---------------------------------------------------------------------------
// f32x2 packed-FMA helpers (PTX-only; ptxas never auto-fuses)
// ---------------------------------------------------------------------------
__device__ __forceinline__ unsigned long long dup2(float x) {
    unsigned long long r;
    asm("mov.b64 %0, {%1, %1};" : "=l"(r) : "f"(x));
    return r;
}
__device__ __forceinline__ void fma2(unsigned long long& d,
                                     unsigned long long a,
                                     unsigned long long b) {
    asm("fma.rn.f32x2 %0, %1, %2, %0;" : "+l"(d) : "l"(a), "l"(b));
}
__device__ __forceinline__ void add2(unsigned long long& d, unsigned long long a) {
    asm("add.rn.f32x2 %0, %0, %1;" : "+l"(d) : "l"(a));
}
__device__ __forceinline__ float2 unpack2(unsigned long long v) {
    float2 f;
    asm("mov.b64 {%0, %1}, %2;" : "=f"(f.x), "=f"(f.y) : "l"(v));
    return f;
}

// ---------------------------------------------------------------------------
// Scratch. Barrier counter and generation flag on SEPARATE 128B L2 lines.
// ---------------------------------------------------------------------------
struct __align__(128) Pad128 { unsigned v; unsigned pad[31]; };
__device__ Pad128   g_count;                        // arrivals (RMW line)
__device__ Pad128   g_gen;                          // generation (read-mostly line)
__device__ float    g_xproj[(size_t)BB * TT * G3];  // [B][T][3N]
__device__ float    g_ht[2][NN * BB];               // transposed hidden [k][b]

// ---------------------------------------------------------------------------
// Kernel 1: x_proj = h_enc @ W_ih^T + b_ih. 128x128x16 tiles, 8x8 microtile,
// f32x2-packed j. Block (0,0) also resets barrier + zeroes h0 (every replay).
// ---------------------------------------------------------------------------
__global__ void __launch_bounds__(256) xproj_kernel(
    const float* __restrict__ A,     // [64000][512]
    const float* __restrict__ Wih,   // [1536][512]
    const float* __restrict__ bih,   // [1536]
    float* __restrict__ C)           // [64000][1536]
{
    __shared__ float As[16][128];
    __shared__ float Bs[16][128];

    const int tid   = threadIdx.x;
    const int mBase = blockIdx.y * 128;
    const int nBase = blockIdx.x * 128;
    const int tx = tid & 15;
    const int ty = tid >> 4;

    if (blockIdx.x == 0 && blockIdx.y == 0) {
        if (tid == 0) { g_count.v = 0u; g_gen.v = 0u; }
        for (int j = tid; j < NN * BB; j += 256) g_ht[0][j] = 0.0f;
    }

    unsigned long long acc2[8][4];
#pragma unroll
    for (int i = 0; i < 8; i++)
#pragma unroll
        for (int j = 0; j < 4; j++) acc2[i][j] = 0ull;

    const int lr = tid >> 2;
    const int lk = (tid & 3) << 2;
    const float* Aptr = A   + (size_t)(mBase + lr) * NN + lk;
    const float* Bptr = Wih + (size_t)(nBase + lr) * NN + lk;

    for (int kt = 0; kt < NN; kt += 16) {
        const float4 a0 = *(const float4*)(Aptr + kt);
        const float4 a1 = *(const float4*)(Aptr + 64 * NN + kt);
        const float4 b0 = *(const float4*)(Bptr + kt);
        const float4 b1 = *(const float4*)(Bptr + 64 * NN + kt);
        __syncthreads();
        As[lk + 0][lr] = a0.x; As[lk + 1][lr] = a0.y; As[lk + 2][lr] = a0.z; As[lk + 3][lr] = a0.w;
        As[lk + 0][64 + lr] = a1.x; As[lk + 1][64 + lr] = a1.y; As[lk + 2][64 + lr] = a1.z; As[lk + 3][64 + lr] = a1.w;
        Bs[lk + 0][lr] = b0.x; Bs[lk + 1][lr] = b0.y; Bs[lk + 2][lr] = b0.z; Bs[lk + 3][lr] = b0.w;
        Bs[lk + 0][64 + lr] = b1.x; Bs[lk + 1][64 + lr] = b1.y; Bs[lk + 2][64 + lr] = b1.z; Bs[lk + 3][64 + lr] = b1.w;
        __syncthreads();
#pragma unroll
        for (int k = 0; k < 16; k++) {
            float af[8];
            *(float4*)&af[0] = *(const float4*)&As[k][ty * 4];
            *(float4*)&af[4] = *(const float4*)&As[k][64 + ty * 4];
            unsigned long long b2[4];
            *(uint4*)&b2[0] = *(const uint4*)&Bs[k][tx * 4];
            *(uint4*)&b2[2] = *(const uint4*)&Bs[k][64 + tx * 4];
#pragma unroll
            for (int i = 0; i < 8; i++) {
                const unsigned long long ad = dup2(af[i]);
#pragma unroll
                for (int j = 0; j < 4; j++) fma2(acc2[i][j], ad, b2[j]);
            }
        }
    }

    float bias[8];
#pragma unroll
    for (int j = 0; j < 8; j++) {
        int col = nBase + ((j < 4) ? (tx * 4 + j) : (64 + tx * 4 + (j - 4)));
        bias[j] = __ldg(&bih[col]);
    }
#pragma unroll
    for (int i = 0; i < 8; i++) {
        float a[8];
#pragma unroll
        for (int j = 0; j < 4; j++) {
            const float2 v = unpack2(acc2[i][j]);
            a[2 * j] = v.x; a[2 * j + 1] = v.y;
        }
        int row = mBase + ((i < 4) ? (ty * 4 + i) : (64 + ty * 4 + (i - 4)));
        float* cp = C + (size_t)row * G3 + nBase;
        *(float4*)(cp + tx * 4) =
            make_float4(a[0] + bias[0], a[1] + bias[1], a[2] + bias[2], a[3] + bias[3]);
        *(float4*)(cp + 64 + tx * 4) =
            make_float4(a[4] + bias[4], a[5] + bias[5], a[6] + bias[6], a[7] + bias[7]);
    }
}

// ---------------------------------------------------------------------------
// Kernel 2: persistent cooperative GRU scan.
//   128 CTAs x 256 threads. thread=(kq 0..3, nn 0..3, b4 0..15): 128-k chunk,
//   one n-col, 4 batches, f32x2 packed -> 6 FFMA2 per k.
//   h READS: L1-cached (4x nn-reuse per CTA); refreshed once per step by the
//   acquire __threadfence (CCTL.IVALL) after the grid barrier.
//   h WRITES: __stcg (L2-direct); release ordering by the acq_rel arrival.
// ---------------------------------------------------------------------------
__global__ void __launch_bounds__(256) gru_scan_kernel(
    const float* __restrict__ Whh,   // [1536][512]
    const float* __restrict__ bhh,   // [1536]
    float* __restrict__ out)         // [B][T][N]
{
    __shared__ unsigned long long wsd[12][514];       // dup'd W: [gate*4+jn][k]
    __shared__ float xs[3][4][64];                    // x_t: [gate][nn][b]
    __shared__ unsigned long long red[4][3][4][32];   // [kq][gate][nn][bpair]
    __shared__ float hs[4][64];                       // h_new: [nn][b]

    const int tid = threadIdx.x;
    const int n0  = blockIdx.x * 4;
    const int kq  = tid >> 6;
    const int nn  = (tid >> 4) & 3;
    const int b4  = tid & 15;

    // Load + duplicate W_hh slice once
    for (int i = tid; i < 12 * 512; i += 256) {
        const int row = i >> 9;            // gate*4 + jn
        const int k   = i & 511;
        const int gate = row >> 2;
        const int jn   = row & 3;
        wsd[row][k] = dup2(__ldg(&Whh[(size_t)(gate * NN + n0 + jn) * NN + k]));
    }

    // Epilogue biases (tid<128: en = tid>>5)
    float bhr = 0.f, bhz = 0.f, bhn = 0.f;
    if (tid < 128) {
        const int en = tid >> 5;
        bhr = __ldg(&bhh[n0 + en]);
        bhz = __ldg(&bhh[NN + n0 + en]);
        bhn = __ldg(&bhh[2 * NN + n0 + en]);
    }

    const unsigned long long* wr = &wsd[nn][kq * 128];
    const unsigned long long* wz = &wsd[4 + nn][kq * 128];
    const unsigned long long* wn = &wsd[8 + nn][kq * 128];
    __syncthreads();

    for (int t = 0; t < TT; t++) {
        const float* __restrict__ hcur = g_ht[t & 1];
        float*       __restrict__ hnxt = g_ht[(t & 1) ^ 1];

        // Stage x_proj[:, t, slice] into SMEM (latency hidden under GEMM)
        if (tid < 192) {
            const int grp = tid >> 6;
            const int bb  = tid & 63;
            const float4 xv = __ldg((const float4*)(
                g_xproj + (size_t)(bb * TT + t) * G3 + grp * NN + n0));
            xs[grp][0][bb] = xv.x; xs[grp][1][bb] = xv.y;
            xs[grp][2][bb] = xv.z; xs[grp][3][bb] = xv.w;
        }

        // Partial gates over this thread's 128-k chunk, 4 batches (f32x2).
        // Plain (L1-cached) h loads: 4x reuse across nn-subgroups.
        unsigned long long ar01 = 0ull, ar23 = 0ull;
        unsigned long long az01 = 0ull, az23 = 0ull;
        unsigned long long an01 = 0ull, an23 = 0ull;
        const float* hk = hcur + kq * 128 * BB + b4 * 4;
#pragma unroll 8
        for (int k = 0; k < 128; k++) {
            const ulonglong2 hv = *(const ulonglong2*)(hk + (size_t)k * BB);
            const unsigned long long w0 = wr[k];
            const unsigned long long w1 = wz[k];
            const unsigned long long w2 = wn[k];
            fma2(ar01, hv.x, w0); fma2(ar23, hv.y, w0);
            fma2(az01, hv.x, w1); fma2(az23, hv.y, w1);
            fma2(an01, hv.x, w2); fma2(an23, hv.y, w2);
        }
        *(ulonglong2*)&red[kq][0][nn][2 * b4] = make_ulonglong2(ar01, ar23);
        *(ulonglong2*)&red[kq][1][nn][2 * b4] = make_ulonglong2(az01, az23);
        *(ulonglong2*)&red[kq][2][nn][2 * b4] = make_ulonglong2(an01, an23);
        __syncthreads();

        // Epilogue: 128 threads, 2 batches each; writes transposed h directly
        if (tid < 128) {
            const int en = tid >> 5;    // n-col 0..3
            const int eb = tid & 31;    // batch pair
            unsigned long long sr = red[0][0][en][eb];
            unsigned long long sz = red[0][1][en][eb];
            unsigned long long sq = red[0][2][en][eb];
#pragma unroll
            for (int q = 1; q < 4; q++) {
                add2(sr, red[q][0][en][eb]);
                add2(sz, red[q][1][en][eb]);
                add2(sq, red[q][2][en][eb]);
            }
            const float2 arf = unpack2(sr);
            const float2 azf = unpack2(sz);
            const float2 aqf = unpack2(sq);
            const float2 hp = *(const float2*)(hcur + (n0 + en) * BB + eb * 2);
            const float2 xr = *(const float2*)&xs[0][en][eb * 2];
            const float2 xz = *(const float2*)&xs[1][en][eb * 2];
            const float2 xn = *(const float2*)&xs[2][en][eb * 2];

            const float r0  = 1.0f / (1.0f + __expf(-(xr.x + arf.x + bhr)));
            const float z0  = 1.0f / (1.0f + __expf(-(xz.x + azf.x + bhz)));
            const float n0v = tanhf(xn.x + r0 * (aqf.x + bhn));
            const float h0  = (1.0f - z0) * n0v + z0 * hp.x;

            const float r1  = 1.0f / (1.0f + __expf(-(xr.y + arf.y + bhr)));
            const float z1  = 1.0f / (1.0f + __expf(-(xz.y + azf.y + bhz)));
            const float n1v = tanhf(xn.y + r1 * (aqf.y + bhn));
            const float h1  = (1.0f - z1) * n1v + z1 * hp.y;

            // Transposed state write: L2-direct, float2 coalesced
            __stcg((float2*)(hnxt + (n0 + en) * BB + eb * 2), make_float2(h0, h1));
            hs[en][eb * 2 + 0] = h0;
            hs[en][eb * 2 + 1] = h1;
        }
        __syncthreads();   // hnxt + hs complete; barrier arrival may proceed

        // Out-writeback OVERLAPS the grid barrier (out is never re-read).
        if (tid < 64) {
            const int b = tid;
            __stcg((float4*)(out + (size_t)(b * TT + t) * NN + n0),
                   make_float4(hs[0][b], hs[1][b], hs[2][b], hs[3][b]));
        }

        // Grid barrier: acq_rel arrival (release: orders the stcg h writes),
        // release-publish g_gen, acquire-poll. Then ONE acquire fence for L1.
        if (t < TT - 1) {
            if (tid == 0) {
                const unsigned target = (unsigned)(t + 1);
                unsigned arrived;
                asm volatile("atom.acq_rel.gpu.global.add.u32 %0, [%1], %2;"
                             : "=r"(arrived) : "l"(&g_count.v), "r"(1u) : "memory");
                if (arrived + 1u == target * (unsigned)GRID_SCAN) {
                    asm volatile("st.release.gpu.global.u32 [%0], %1;"
                                 :: "l"(&g_gen.v), "r"(target) : "memory");
                } else {
                    unsigned g;
                    while (true) {
                        asm volatile("ld.acquire.gpu.global.u32 %0, [%1];"
                                     : "=r"(g) : "l"(&g_gen.v) : "memory");
                        if (g >= target) break;
                        __nanosleep(32);
                    }
                }
            }
            __syncthreads();
            __threadfence();   // acquire: CCTL.IVALL so L1 h lines refresh
        }
    }
}

// ---------------------------------------------------------------------------
// Launch
// ---------------------------------------------------------------------------
extern "C" void kernel_launch(void* const* d_in, const int* in_sizes, int n_in,
                              void* d_out, int out_size) {
    const float* h_enc = (const float*)d_in[0];
    const float* W_ih  = (const float*)d_in[1];
    const float* W_hh  = (const float*)d_in[2];
    const float* b_ih  = (const float*)d_in[3];
    const float* b_hh  = (const float*)d_in[4];
    float* out = (float*)d_out;

    float* xproj_ptr = nullptr;
    cudaGetSymbolAddress((void**)&xproj_ptr, g_xproj);

    dim3 grid(G3 / 128, (BB * TT) / 128);
    xproj_kernel<<<grid, 256>>>(h_enc, W_ih, b_ih, xproj_ptr);
    gru_scan_kernel<<<GRID_SCAN, 256>>>(W_hh, b_hh, out);
}